// round 17
// baseline (speedup 1.0000x reference)
#include <cuda_runtime.h>
#include <math.h>

#define BATCH      256
#define T_LEN      65536
#define L_CHUNK    32
#define W_WARM     32                      // window = exactly previous chunk
#define CPB        128                     // threads per block (4 warps)
#define SPAN       1024                    // floats per warp-span (32 chunks)
#define REGION     (CPB * L_CHUNK)         // 4096 floats per block
#define RB_PER_ROW (T_LEN / REGION)        // 16 blocks per batch row
#define NBLK       (BATCH * RB_PER_ROW)    // 4096 blocks
#define SPAN_W     (SPAN + W_WARM)         // span + pad words

// ---- Butterworth(4, 0.5) coefficients as compile-time literals ----
#define KD   0.010209481f
#define CB0  (KD)
#define CB1  (4.0f * KD)
#define CB2  (6.0f * KD)
#define CB3  (4.0f * KD)
#define CB4  (KD)
#define CNA1 ( 1.96842778f)     // -a1
#define CNA2 (-1.73586071f)     // -a2
#define CNA3 ( 0.72447081f)     // -a3
#define CNA4 (-0.12038960f)     // -a4

struct Params {
    float4 wq4[W_WARM];            // warmup weights w_j = A^(W-1-j) g (const space)
};

// 16B-granule swizzle within a warp-span: word (chunk c, sample j) ->
// c*32 + (j ^ ((c&7)<<2)). Aligned float4 groups stay contiguous; all
// 128-bit smem phases below are bank-conflict-free (pad read: one 2-way).
__device__ __forceinline__ int sidx4(int c, int j) {
    return c * L_CHUNK + (j ^ ((c & 7) << 2));
}

__device__ __forceinline__ void cpa16(unsigned dst_smem, const void* src) {
    asm volatile("cp.async.cg.shared.global [%0], [%1], 16;\n"
                 :: "r"(dst_smem), "l"(src));
}

// One DF2T step, coefficient multiplies in FFMA-imm form.
__device__ __forceinline__ float iir_step(float xv, float& z0, float& z1,
                                          float& z2, float& z3) {
    float yv = fmaf(CB0, xv, z0);
    z0 = fmaf(CB1, xv, z1); z0 = fmaf(CNA1, yv, z0);
    z1 = fmaf(CB2, xv, z2); z1 = fmaf(CNA2, yv, z1);
    z2 = fmaf(CB3, xv, z3); z2 = fmaf(CNA3, yv, z2);
    z3 = CB4 * xv;          z3 = fmaf(CNA4, yv, z3);
    return yv;
}

__global__ void __launch_bounds__(CPB, 13) fused_kernel(const float* __restrict__ x,
                                                        float* __restrict__ y,
                                                        Params P) {
    // One private span (+32-float warmup pad) per warp. No block barriers:
    // warps drift through stage/compute/store phases independently.
    __shared__ float4 smv[(4 * SPAN_W) / 4];
    float* smw = reinterpret_cast<float*>(smv);

    const int t    = threadIdx.x;
    const int w    = t >> 5;
    const int l    = t & 31;
    const int blk  = blockIdx.x;
    const int rb   = blk & (RB_PER_ROW - 1);
    const size_t gspan = (size_t)(blk >> 4) * T_LEN + (size_t)rb * REGION
                       + (size_t)w * SPAN;
    float* sm = smw + w * SPAN_W;          // this warp's span base

    // ---- stage: coalesced 16B cp.async -> swizzled warp-private smem ----
    const float4* xin = reinterpret_cast<const float4*>(x + gspan);
    unsigned smb = (unsigned)__cvta_generic_to_shared(sm);
#pragma unroll
    for (int i = 0; i < SPAN / (4 * 32); i++) {      // 8 iters
        int vidx = i * 32 + l;
        int c = vidx >> 3;                // 8 float4 per chunk
        int j = (vidx & 7) * 4;
        cpa16(smb + sidx4(c, j) * 4u, xin + vidx);
    }
    {   // pad: x[span_start-32 .. -1]; zero only at the very start of a row
        const bool has_prev = (rb != 0) || (w != 0);
        if (l < W_WARM / 4) {
            if (has_prev)
                cpa16(smb + (SPAN + 4 * l) * 4u,
                      reinterpret_cast<const float4*>(x + gspan - W_WARM) + l);
            else
                reinterpret_cast<float4*>(sm + SPAN)[l] =
                    make_float4(0.f, 0.f, 0.f, 0.f);
        }
    }
    asm volatile("cp.async.commit_group;\n");
    asm volatile("cp.async.wait_group 0;\n");
    __syncwarp();

    // ---- warmup: state from previous 32 samples (prev chunk or pad) ----
    float z0 = 0.f, z1 = 0.f, z2 = 0.f, z3 = 0.f;
    {
        const int wbase = (l > 0) ? (l - 1) * L_CHUNK : SPAN;
        const int wk    = (l > 0) ? ((l - 1) & 7) << 2 : 0;
#pragma unroll
        for (int q = 0; q < W_WARM / 4; q++) {
            float4 xv = *reinterpret_cast<const float4*>(&sm[wbase + ((4 * q) ^ wk)]);
            float4 w0 = P.wq4[4 * q + 0], w1 = P.wq4[4 * q + 1];
            float4 w2 = P.wq4[4 * q + 2], w3 = P.wq4[4 * q + 3];
            z0 = fmaf(w0.x, xv.x, z0); z1 = fmaf(w0.y, xv.x, z1);
            z2 = fmaf(w0.z, xv.x, z2); z3 = fmaf(w0.w, xv.x, z3);
            z0 = fmaf(w1.x, xv.y, z0); z1 = fmaf(w1.y, xv.y, z1);
            z2 = fmaf(w1.z, xv.y, z2); z3 = fmaf(w1.w, xv.y, z3);
            z0 = fmaf(w2.x, xv.z, z0); z1 = fmaf(w2.y, xv.z, z1);
            z2 = fmaf(w2.z, xv.z, z2); z3 = fmaf(w2.w, xv.z, z3);
            z0 = fmaf(w3.x, xv.w, z0); z1 = fmaf(w3.y, xv.w, z1);
            z2 = fmaf(w3.z, xv.w, z2); z3 = fmaf(w3.w, xv.w, z3);
        }
    }
    __syncwarp();      // all warmup reads done before in-place overwrite

    // ---- main: DF2T over own chunk (lane l owns chunk l), y in place ----
#pragma unroll
    for (int q = 0; q < L_CHUNK / 4; q++) {
        float4* ap = reinterpret_cast<float4*>(&sm[sidx4(l, 4 * q)]);
        float4 xv = *ap;
        float4 ov;
        ov.x = iir_step(xv.x, z0, z1, z2, z3);
        ov.y = iir_step(xv.y, z0, z1, z2, z3);
        ov.z = iir_step(xv.z, z0, z1, z2, z3);
        ov.w = iir_step(xv.w, z0, z1, z2, z3);
        *ap = ov;
    }
    __syncwarp();

    // ---- output: swizzled LDS.128 -> coalesced STG.128 ----
    float4* yout = reinterpret_cast<float4*>(y + gspan);
#pragma unroll
    for (int i = 0; i < SPAN / (4 * 32); i++) {
        int vidx = i * 32 + l;
        int c = vidx >> 3;
        int j = (vidx & 7) * 4;
        yout[vidx] = *reinterpret_cast<const float4*>(&sm[sidx4(c, j)]);
    }
}

// ---------------- host ----------------

extern "C" void kernel_launch(void* const* d_in, const int* in_sizes, int n_in,
                              void* d_out, int out_size) {
    const float* x = (const float*)d_in[0];
    float* y = (float*)d_out;

    // Same coefficients as the device literals, in double for weight generation.
    const double kd = 0.010209481;
    const double bcoef[5] = { kd, 4.0 * kd, 6.0 * kd, 4.0 * kd, kd };
    const double acoef[5] = { 1.0, -1.96842778, 1.73586071,
                              -0.72447081, 0.12038960 };

    // state transition: z' = A z + g x  (DF2T with y eliminated)
    double A[16] = {0};
    for (int i = 0; i < 4; i++) {
        A[i * 4 + 0] -= acoef[i + 1];
        if (i < 3) A[i * 4 + (i + 1)] += 1.0;
    }
    double g[4];
    for (int i = 0; i < 4; i++) g[i] = bcoef[i + 1] - acoef[i + 1] * bcoef[0];

    Params P;
    // warmup weights: w_j = A^(W-1-j) g  (oldest sample gets highest power)
    double wv[4] = { g[0], g[1], g[2], g[3] };
    for (int j = W_WARM - 1; j >= 0; j--) {
        P.wq4[j] = make_float4((float)wv[0], (float)wv[1],
                               (float)wv[2], (float)wv[3]);
        double nv[4];
        for (int i = 0; i < 4; i++) {
            nv[i] = 0.0;
            for (int k2 = 0; k2 < 4; k2++) nv[i] += A[i * 4 + k2] * wv[k2];
        }
        for (int i = 0; i < 4; i++) wv[i] = nv[i];
    }

    fused_kernel<<<NBLK, CPB>>>(x, y, P);
}